// round 6
// baseline (speedup 1.0000x reference)
#include <cuda_runtime.h>

#define N_NODES 100000
#define N_EDGES 1600000
#define D 64
#define SCAN_NB 391   // 391*256 = 100096 >= N_NODES
#define AROW 65       // padded sA row stride (floats): conflict-free LDS.32

typedef unsigned long long ull;

// Scratch (static __device__ — allocation-free per harness rules)
__device__ int   g_is64;
__device__ int   g_deg[N_NODES];
__device__ int   g_rowoff[N_NODES + 1];
__device__ int   g_cursor[N_NODES];
__device__ float g_dinv[N_NODES];
__device__ int   g_srcidx[N_EDGES];
__device__ int   g_bsum[512];
__device__ float g_H[N_NODES * D];   // layer-1 hidden

// ---------- packed f32x2 helpers ----------
__device__ __forceinline__ ull fma2(ull a, ull b, ull c) {
    ull d;
    asm("fma.rn.f32x2 %0, %1, %2, %3;" : "=l"(d) : "l"(a), "l"(b), "l"(c));
    return d;
}
__device__ __forceinline__ ull pack2(float x, float y) {
    ull d;
    asm("mov.b64 %0, {%1, %2};" : "=l"(d) : "f"(x), "f"(y));
    return d;
}
__device__ __forceinline__ void unpack2(ull v, float& x, float& y) {
    asm("mov.b64 {%0, %1}, %2;" : "=f"(x), "=f"(y) : "l"(v));
}

__device__ __forceinline__ int clampN(int v) {
    return min(max(v, 0), N_NODES - 1);
}
__device__ __forceinline__ int load_id(const void* ei, long long idx, int is64) {
    int v = is64 ? (int)((const long long*)ei)[idx] : ((const int*)ei)[idx];
    return clampN(v);
}

// ---------- init: zero degrees + dtype detect (thread 0 of block 0) ----------
__global__ void k_init(const int* __restrict__ ei32) {
    int i = blockIdx.x * blockDim.x + threadIdx.x;
    if (i < N_NODES) g_deg[i] = 0;
    if (i == 0) {
        int odd_zero = 1;
#pragma unroll
        for (int j = 1; j < 64; j += 2)
            if (ei32[j] != 0) odd_zero = 0;
        g_is64 = odd_zero;
    }
}

__global__ void k_hist(const void* __restrict__ ei) {
    int e = blockIdx.x * blockDim.x + threadIdx.x;
    if (e < N_EDGES) {
        int is64 = g_is64;
        int dst = load_id(ei, (long long)N_EDGES + e, is64);
        atomicAdd(&g_deg[dst], 1);
    }
}

__global__ void k_scan1() {
    __shared__ int sh[256];
    int i = blockIdx.x * 256 + threadIdx.x;
    int t = threadIdx.x;
    sh[t] = (i < N_NODES) ? g_deg[i] : 0;
    __syncthreads();
    for (int off = 128; off > 0; off >>= 1) {
        if (t < off) sh[t] += sh[t + off];
        __syncthreads();
    }
    if (t == 0) g_bsum[blockIdx.x] = sh[0];
}

// per-block: scan 391 block sums (redundant, cheap) + local scan + write CSR
__global__ void k_scan23() {
    __shared__ int sb2[512];
    __shared__ int sh[256];
    int b = blockIdx.x;
    int t = threadIdx.x;
    // scan block sums into sb2 (512-wide Hillis-Steele over 2 elems/thread)
    sb2[t]       = (t < SCAN_NB) ? g_bsum[t] : 0;
    sb2[t + 256] = (t + 256 < SCAN_NB) ? g_bsum[t + 256] : 0;
    __syncthreads();
    for (int off = 1; off < 512; off <<= 1) {
        int v0 = (t >= off) ? sb2[t - off] : 0;
        int v1 = (t + 256 >= off) ? sb2[t + 256 - off] : 0;
        __syncthreads();
        sb2[t] += v0;
        sb2[t + 256] += v1;
        __syncthreads();
    }
    int boff = (b == 0) ? 0 : sb2[b - 1];
    int i = b * 256 + t;
    int d = (i < N_NODES) ? g_deg[i] : 0;
    sh[t] = d;
    __syncthreads();
    for (int off = 1; off < 256; off <<= 1) {
        int v = (t >= off) ? sh[t - off] : 0;
        __syncthreads();
        sh[t] += v;
        __syncthreads();
    }
    if (i < N_NODES) {
        int excl = sh[t] - d + boff;
        g_rowoff[i] = excl;
        g_cursor[i] = excl;
        g_dinv[i] = 1.0f / (float)max(d, 1);
    }
    if (i == 0) g_rowoff[N_NODES] = N_EDGES;
}

__global__ void k_fill(const void* __restrict__ ei) {
    int e = blockIdx.x * blockDim.x + threadIdx.x;
    if (e < N_EDGES) {
        int is64 = g_is64;
        int dst = load_id(ei, (long long)N_EDGES + e, is64);
        int src = load_id(ei, e, is64);
        int pos = atomicAdd(&g_cursor[dst], 1);
        pos = min(max(pos, 0), N_EDGES - 1);
        g_srcidx[pos] = src;
    }
}

// ---------- fused layer: mean-agg (block's 256 nodes -> SMEM) + dual-GEMV ----------
// dyn smem: sA[256*AROW] | sWl[4096] | sWr[4096] | sb[64]
template <bool FIRST>
__global__ void __launch_bounds__(256)
k_layer(const float* __restrict__ xext,
        const float* __restrict__ Wl, const float* __restrict__ bias,
        const float* __restrict__ Wr, float* __restrict__ outext) {
    extern __shared__ float smem[];
    float* sA  = smem;                    // 256*65 = 16640 floats
    float* sWl = sA + 256 * AROW;
    float* sWr = sWl + 4096;
    float* sb  = sWr + 4096;

    const float* __restrict__ X = FIRST ? xext : (const float*)g_H;
    float* out = FIRST ? (float*)g_H : outext;
    int tid = threadIdx.x;
    int w = tid >> 5, lane = tid & 31;
    int base = blockIdx.x * 256;

    // weights (transposed pair-contiguous) — overlaps with gather latency below
    for (int i = tid; i < 4096; i += 256) {
        int j = i >> 6, k = i & 63;
        sWl[k * 64 + j] = Wl[i];
        sWr[k * 64 + j] = Wr[i];
    }
    if (tid < 64) sb[tid] = bias[tid];

    // Phase A: 8 warps, each aggregates 32 of the block's nodes
    for (int r = 0; r < 32; r++) {
        int ln = w * 32 + r;              // local node 0..255
        int node = base + ln;
        if (node >= N_NODES) break;
        int s = g_rowoff[node], e = g_rowoff[node + 1];
        float ax = 0.f, ay = 0.f;
        int i = s;
        for (; i + 3 < e; i += 4) {
            int s0 = g_srcidx[i], s1 = g_srcidx[i + 1];
            int s2 = g_srcidx[i + 2], s3 = g_srcidx[i + 3];
            float2 v0 = *(const float2*)&X[s0 * D + lane * 2];
            float2 v1 = *(const float2*)&X[s1 * D + lane * 2];
            float2 v2 = *(const float2*)&X[s2 * D + lane * 2];
            float2 v3 = *(const float2*)&X[s3 * D + lane * 2];
            ax += v0.x + v1.x + v2.x + v3.x;
            ay += v0.y + v1.y + v2.y + v3.y;
        }
        for (; i < e; i++) {
            int s0 = g_srcidx[i];
            float2 v = *(const float2*)&X[s0 * D + lane * 2];
            ax += v.x; ay += v.y;
        }
        float di = g_dinv[node];
        sA[ln * AROW + lane * 2]     = ax * di;
        sA[ln * AROW + lane * 2 + 1] = ay * di;
    }
    __syncthreads();

    // Phase B: thread tid -> node base+tid, dual GEMV with FFMA2
    int node = base + tid;
    if (node >= N_NODES) return;

    ull acc[32];
#pragma unroll
    for (int j = 0; j < 32; j++) acc[j] = pack2(sb[2 * j], sb[2 * j + 1]);

    const float4* Xr = (const float4*)(X + node * D);
    const float* Ar = sA + tid * AROW;

#pragma unroll 1
    for (int kq = 0; kq < 16; kq++) {
        float4 xq = Xr[kq];
        float fa0 = Ar[kq * 4], fa1 = Ar[kq * 4 + 1];
        float fa2 = Ar[kq * 4 + 2], fa3 = Ar[kq * 4 + 3];
        float fa[4] = {fa0, fa1, fa2, fa3};
        float fx[4] = {xq.x, xq.y, xq.z, xq.w};
#pragma unroll
        for (int kk = 0; kk < 4; kk++) {
            int k = kq * 4 + kk;
            ull pa = pack2(fa[kk], fa[kk]);
            ull px = pack2(fx[kk], fx[kk]);
            const ulonglong2* wlp = (const ulonglong2*)&sWl[k * 64];
            const ulonglong2* wrp = (const ulonglong2*)&sWr[k * 64];
#pragma unroll
            for (int jp = 0; jp < 16; jp++) {
                ulonglong2 wl = wlp[jp];   // LDS.128 broadcast
                ulonglong2 wr = wrp[jp];
                acc[2 * jp]     = fma2(wl.x, pa, fma2(wr.x, px, acc[2 * jp]));
                acc[2 * jp + 1] = fma2(wl.y, pa, fma2(wr.y, px, acc[2 * jp + 1]));
            }
        }
    }

    float4* o = (float4*)(out + node * D);
#pragma unroll
    for (int q = 0; q < 16; q++) {
        float r0, r1, r2, r3;
        unpack2(acc[2 * q], r0, r1);
        unpack2(acc[2 * q + 1], r2, r3);
        if (FIRST) {
            r0 = fmaxf(r0, 0.f); r1 = fmaxf(r1, 0.f);
            r2 = fmaxf(r2, 0.f); r3 = fmaxf(r3, 0.f);
        }
        o[q] = make_float4(r0, r1, r2, r3);
    }
}

extern "C" void kernel_launch(void* const* d_in, const int* in_sizes, int n_in,
                              void* d_out, int out_size) {
    const float* x   = (const float*)d_in[0];
    const void*  ei  = d_in[1];
    const float* W1l = (const float*)d_in[2];
    const float* b1  = (const float*)d_in[3];
    const float* W1r = (const float*)d_in[4];
    const float* W2l = (const float*)d_in[5];
    const float* b2  = (const float*)d_in[6];
    const float* W2r = (const float*)d_in[7];
    float* out = (float*)d_out;

    const int SMEM_BYTES = (256 * AROW + 4096 + 4096 + 64) * 4;  // 99584 B
    static int s_attr_done = 0;
    if (!s_attr_done) {   // host-side attribute set; no device work, deterministic
        cudaFuncSetAttribute(k_layer<true>,
            cudaFuncAttributeMaxDynamicSharedMemorySize, SMEM_BYTES);
        cudaFuncSetAttribute(k_layer<false>,
            cudaFuncAttributeMaxDynamicSharedMemorySize, SMEM_BYTES);
        s_attr_done = 1;
    }

    k_init<<<SCAN_NB, 256>>>((const int*)ei);
    k_hist<<<(N_EDGES + 255) / 256, 256>>>(ei);
    k_scan1<<<SCAN_NB, 256>>>();
    k_scan23<<<SCAN_NB, 256>>>();
    k_fill<<<(N_EDGES + 255) / 256, 256>>>(ei);

    k_layer<true><<<SCAN_NB, 256, SMEM_BYTES>>>(x, W1l, b1, W1r, nullptr);
    k_layer<false><<<SCAN_NB, 256, SMEM_BYTES>>>(x, W2l, b2, W2r, out);
}

// round 7
// speedup vs baseline: 1.5870x; 1.5870x over previous
#include <cuda_runtime.h>

#define N_NODES 100000
#define N_EDGES 1600000
#define D 64
#define SCAN_NB 391   // 391*256 = 100096 >= N_NODES

typedef unsigned long long ull;

// Scratch (static __device__ — allocation-free per harness rules)
__device__ int   g_is64;
__device__ int   g_deg[N_NODES];
__device__ int   g_rowoff[N_NODES + 1];
__device__ int   g_cursor[N_NODES];
__device__ float g_dinv[N_NODES];
__device__ int   g_srcidx[N_EDGES];
__device__ int   g_bsum[512];
__device__ float g_A[N_NODES * D];   // aggregated (mean) neighbor features
__device__ float g_H[N_NODES * D];   // layer-1 hidden

// ---------- packed f32x2 helpers ----------
__device__ __forceinline__ ull fma2(ull a, ull b, ull c) {
    ull d;
    asm("fma.rn.f32x2 %0, %1, %2, %3;" : "=l"(d) : "l"(a), "l"(b), "l"(c));
    return d;
}
__device__ __forceinline__ ull pack2(float x, float y) {
    ull d;
    asm("mov.b64 %0, {%1, %2};" : "=l"(d) : "f"(x), "f"(y));
    return d;
}
__device__ __forceinline__ void unpack2(ull v, float& x, float& y) {
    asm("mov.b64 {%0, %1}, %2;" : "=f"(x), "=f"(y) : "l"(v));
}

__device__ __forceinline__ int clampN(int v) {
    return min(max(v, 0), N_NODES - 1);
}
__device__ __forceinline__ int load_id(const void* ei, long long idx, int is64) {
    int v = is64 ? (int)((const long long*)ei)[idx] : ((const int*)ei)[idx];
    return clampN(v);
}

// ---------- init: zero degrees + dtype detect ----------
__global__ void k_init(const int* __restrict__ ei32) {
    int i = blockIdx.x * blockDim.x + threadIdx.x;
    if (i < N_NODES) g_deg[i] = 0;
    if (i == 0) {
        int odd_zero = 1;
#pragma unroll
        for (int j = 1; j < 64; j += 2)
            if (ei32[j] != 0) odd_zero = 0;
        g_is64 = odd_zero;
    }
}

__global__ void k_hist(const void* __restrict__ ei) {
    int e = blockIdx.x * blockDim.x + threadIdx.x;
    if (e < N_EDGES) {
        int is64 = g_is64;
        int dst = load_id(ei, (long long)N_EDGES + e, is64);
        atomicAdd(&g_deg[dst], 1);
    }
}

__global__ void k_scan1() {
    __shared__ int sh[256];
    int i = blockIdx.x * 256 + threadIdx.x;
    int t = threadIdx.x;
    sh[t] = (i < N_NODES) ? g_deg[i] : 0;
    __syncthreads();
    for (int off = 128; off > 0; off >>= 1) {
        if (t < off) sh[t] += sh[t + off];
        __syncthreads();
    }
    if (t == 0) g_bsum[blockIdx.x] = sh[0];
}

// per-block: redundant scan of 391 block sums + local scan + write CSR arrays
__global__ void k_scan23() {
    __shared__ int sb2[512];
    __shared__ int sh[256];
    int b = blockIdx.x;
    int t = threadIdx.x;
    sb2[t]       = (t < SCAN_NB) ? g_bsum[t] : 0;
    sb2[t + 256] = (t + 256 < SCAN_NB) ? g_bsum[t + 256] : 0;
    __syncthreads();
    for (int off = 1; off < 512; off <<= 1) {
        int v0 = (t >= off) ? sb2[t - off] : 0;
        int v1 = (t + 256 >= off) ? sb2[t + 256 - off] : 0;
        __syncthreads();
        sb2[t] += v0;
        sb2[t + 256] += v1;
        __syncthreads();
    }
    int boff = (b == 0) ? 0 : sb2[b - 1];
    int i = b * 256 + t;
    int d = (i < N_NODES) ? g_deg[i] : 0;
    sh[t] = d;
    __syncthreads();
    for (int off = 1; off < 256; off <<= 1) {
        int v = (t >= off) ? sh[t - off] : 0;
        __syncthreads();
        sh[t] += v;
        __syncthreads();
    }
    if (i < N_NODES) {
        int excl = sh[t] - d + boff;
        g_rowoff[i] = excl;
        g_cursor[i] = excl;
        g_dinv[i] = 1.0f / (float)max(d, 1);
    }
    if (i == 0) g_rowoff[N_NODES] = N_EDGES;
}

__global__ void k_fill(const void* __restrict__ ei) {
    int e = blockIdx.x * blockDim.x + threadIdx.x;
    if (e < N_EDGES) {
        int is64 = g_is64;
        int dst = load_id(ei, (long long)N_EDGES + e, is64);
        int src = load_id(ei, e, is64);
        int pos = atomicAdd(&g_cursor[dst], 1);
        pos = min(max(pos, 0), N_EDGES - 1);
        g_srcidx[pos] = src;
    }
}

// ---------- mean aggregation: warp per node, no atomics ----------
template <bool FIRST>
__global__ void k_agg(const float* __restrict__ xext) {
    const float* __restrict__ feat = FIRST ? xext : (const float*)g_H;
    int gw = (blockIdx.x * blockDim.x + threadIdx.x) >> 5;
    int lane = threadIdx.x & 31;
    if (gw >= N_NODES) return;
    int s = g_rowoff[gw], e = g_rowoff[gw + 1];
    float ax = 0.f, ay = 0.f;
    int i = s;
    for (; i + 3 < e; i += 4) {   // MLP=4: 4 gathers in flight
        int s0 = g_srcidx[i], s1 = g_srcidx[i + 1];
        int s2 = g_srcidx[i + 2], s3 = g_srcidx[i + 3];
        float2 v0 = *(const float2*)&feat[s0 * D + lane * 2];
        float2 v1 = *(const float2*)&feat[s1 * D + lane * 2];
        float2 v2 = *(const float2*)&feat[s2 * D + lane * 2];
        float2 v3 = *(const float2*)&feat[s3 * D + lane * 2];
        ax += v0.x + v1.x + v2.x + v3.x;
        ay += v0.y + v1.y + v2.y + v3.y;
    }
    for (; i < e; i++) {
        int s0 = g_srcidx[i];
        float2 v = *(const float2*)&feat[s0 * D + lane * 2];
        ax += v.x; ay += v.y;
    }
    float di = g_dinv[gw];
    *(float2*)&g_A[gw * D + lane * 2] = make_float2(ax * di, ay * di);
}

// ---------- fused dual-linear: out = A@Wl^T + b + X@Wr^T (+relu) ----------
// 128 threads/block, 2 nodes/thread, packed FFMA2, LDS.128 weight loads,
// one-iteration double-buffered prefetch of A/X quads.
template <bool FIRST>
__global__ void __launch_bounds__(128)
k_dense(const float* __restrict__ xext,
        const float* __restrict__ Wl, const float* __restrict__ bias,
        const float* __restrict__ Wr, float* __restrict__ outext) {
    __shared__ float sWl[64 * 64];
    __shared__ float sWr[64 * 64];
    __shared__ float sb[64];
    const float* __restrict__ X = FIRST ? xext : (const float*)g_H;
    float* out = FIRST ? (float*)g_H : outext;
    int tid = threadIdx.x;
    for (int i = tid; i < 4096; i += 128) {
        int j = i >> 6, k = i & 63;
        sWl[k * 64 + j] = Wl[i];   // sW[k][j] = W[j][k]
        sWr[k * 64 + j] = Wr[i];
    }
    if (tid < 64) sb[tid] = bias[tid];
    __syncthreads();

    int n0 = blockIdx.x * 256 + tid;
    int n1 = n0 + 128;
    bool v0 = n0 < N_NODES, v1 = n1 < N_NODES;
    int m0 = v0 ? n0 : 0, m1 = v1 ? n1 : 0;

    ull acc0[32], acc1[32];
#pragma unroll
    for (int j = 0; j < 32; j++) {
        ull bb = pack2(sb[2 * j], sb[2 * j + 1]);
        acc0[j] = bb; acc1[j] = bb;
    }
    const float4* A0 = (const float4*)(g_A + m0 * D);
    const float4* A1 = (const float4*)(g_A + m1 * D);
    const float4* X0 = (const float4*)(X + m0 * D);
    const float4* X1 = (const float4*)(X + m1 * D);

    float4 a0 = A0[0], xq0 = X0[0], a1 = A1[0], xq1 = X1[0];

#pragma unroll 1
    for (int kq = 0; kq < 16; kq++) {
        float4 na0, nx0, na1, nx1;
        if (kq < 15) {                       // prefetch next quads (LDG in flight
            na0 = A0[kq + 1]; nx0 = X0[kq + 1];   //  during compute below)
            na1 = A1[kq + 1]; nx1 = X1[kq + 1];
        }
        float fa0[4] = {a0.x, a0.y, a0.z, a0.w};
        float fx0[4] = {xq0.x, xq0.y, xq0.z, xq0.w};
        float fa1[4] = {a1.x, a1.y, a1.z, a1.w};
        float fx1[4] = {xq1.x, xq1.y, xq1.z, xq1.w};
#pragma unroll
        for (int kk = 0; kk < 4; kk++) {
            int k = kq * 4 + kk;
            ull pa0 = pack2(fa0[kk], fa0[kk]);
            ull px0 = pack2(fx0[kk], fx0[kk]);
            ull pa1 = pack2(fa1[kk], fa1[kk]);
            ull px1 = pack2(fx1[kk], fx1[kk]);
            const ulonglong2* wlp = (const ulonglong2*)&sWl[k * 64];
            const ulonglong2* wrp = (const ulonglong2*)&sWr[k * 64];
#pragma unroll
            for (int jp = 0; jp < 16; jp++) {
                ulonglong2 wl = wlp[jp];   // LDS.128 broadcast
                ulonglong2 wr = wrp[jp];
                acc0[2 * jp]     = fma2(wl.x, pa0, fma2(wr.x, px0, acc0[2 * jp]));
                acc0[2 * jp + 1] = fma2(wl.y, pa0, fma2(wr.y, px0, acc0[2 * jp + 1]));
                acc1[2 * jp]     = fma2(wl.x, pa1, fma2(wr.x, px1, acc1[2 * jp]));
                acc1[2 * jp + 1] = fma2(wl.y, pa1, fma2(wr.y, px1, acc1[2 * jp + 1]));
            }
        }
        a0 = na0; xq0 = nx0; a1 = na1; xq1 = nx1;
    }

    if (v0) {
        float4* o = (float4*)(out + n0 * D);
#pragma unroll
        for (int q = 0; q < 16; q++) {
            float r0, r1, r2, r3;
            unpack2(acc0[2 * q], r0, r1);
            unpack2(acc0[2 * q + 1], r2, r3);
            if (FIRST) {
                r0 = fmaxf(r0, 0.f); r1 = fmaxf(r1, 0.f);
                r2 = fmaxf(r2, 0.f); r3 = fmaxf(r3, 0.f);
            }
            o[q] = make_float4(r0, r1, r2, r3);
        }
    }
    if (v1) {
        float4* o = (float4*)(out + n1 * D);
#pragma unroll
        for (int q = 0; q < 16; q++) {
            float r0, r1, r2, r3;
            unpack2(acc1[2 * q], r0, r1);
            unpack2(acc1[2 * q + 1], r2, r3);
            if (FIRST) {
                r0 = fmaxf(r0, 0.f); r1 = fmaxf(r1, 0.f);
                r2 = fmaxf(r2, 0.f); r3 = fmaxf(r3, 0.f);
            }
            o[q] = make_float4(r0, r1, r2, r3);
        }
    }
}

extern "C" void kernel_launch(void* const* d_in, const int* in_sizes, int n_in,
                              void* d_out, int out_size) {
    const float* x   = (const float*)d_in[0];
    const void*  ei  = d_in[1];
    const float* W1l = (const float*)d_in[2];
    const float* b1  = (const float*)d_in[3];
    const float* W1r = (const float*)d_in[4];
    const float* W2l = (const float*)d_in[5];
    const float* b2  = (const float*)d_in[6];
    const float* W2r = (const float*)d_in[7];
    float* out = (float*)d_out;

    k_init<<<SCAN_NB, 256>>>((const int*)ei);
    k_hist<<<(N_EDGES + 255) / 256, 256>>>(ei);
    k_scan1<<<SCAN_NB, 256>>>();
    k_scan23<<<SCAN_NB, 256>>>();
    k_fill<<<(N_EDGES + 255) / 256, 256>>>(ei);

    const int DNB = (N_NODES + 255) / 256;   // 391 blocks of 128 threads

    // Layer 1
    k_agg<true><<<(N_NODES * 32 + 255) / 256, 256>>>(x);
    k_dense<true><<<DNB, 128>>>(x, W1l, b1, W1r, nullptr);

    // Layer 2
    k_agg<false><<<(N_NODES * 32 + 255) / 256, 256>>>(x);
    k_dense<false><<<DNB, 128>>>(x, W2l, b2, W2r, out);
}